// round 1
// baseline (speedup 1.0000x reference)
#include <cuda_runtime.h>
#include <cuda_bf16.h>
#include <cstdint>

// Problem constants
#define MTOK   65536      // B*T = 16*4096
#define IDIM   512
#define HDIM   1024
#define KSEL   256        // 2*CDIM

// ---------------------------------------------------------------------------
// Scratch: two ping-pong activation buffers, each [65536, 1024] fp32 (256 MB).
// __device__ globals (no runtime allocation — allocation guards are enforced).
// ---------------------------------------------------------------------------
__device__ float g_bufA[(size_t)MTOK * HDIM];
__device__ float g_bufB[(size_t)MTOK * HDIM];

// ---------------------------------------------------------------------------
// SGEMM: C[M,N] = act( A[M,K] @ W[K,N] + bias[N] ), optional mask-zeroing.
// BM=BN=128, BK=8, 256 threads, 8x8 per-thread microtile.
// All dims are multiples of the tile sizes (M=65536, N in {512,1024},
// K in {512,1024}) -> no bounds checks.
// ---------------------------------------------------------------------------
__global__ __launch_bounds__(256)
void sgemm_kernel(const float* __restrict__ A, const float* __restrict__ W,
                  const float* __restrict__ bias, const float* __restrict__ mask,
                  float* __restrict__ C, int M, int N, int K, int do_relu)
{
    __shared__ __align__(16) float As[8][132];   // transposed A tile, padded
    __shared__ __align__(16) float Bs[8][132];   // B tile, padded

    const int tid = threadIdx.x;
    const int bm = blockIdx.y * 128;
    const int bn = blockIdx.x * 128;

    // A-tile load mapping: 128 rows x 8 cols = 256 float4 (one per thread)
    const int aRow = tid >> 1;            // 0..127
    const int aCol = (tid & 1) << 2;      // 0 or 4
    // B-tile load mapping: 8 rows x 128 cols = 256 float4
    const int bRow = tid >> 5;            // 0..7
    const int bCol = (tid & 31) << 2;     // 0..124

    const float* Aptr = A + (size_t)(bm + aRow) * K + aCol;
    const float* Bptr = W + (size_t)bRow * N + bn + bCol;

    const int tx = tid & 15;              // 0..15  -> col group
    const int ty = tid >> 4;              // 0..15  -> row group
    const int mro = ty * 8;
    const int nco = tx * 8;

    float acc[8][8];
    #pragma unroll
    for (int i = 0; i < 8; i++)
        #pragma unroll
        for (int j = 0; j < 8; j++) acc[i][j] = 0.0f;

    for (int k0 = 0; k0 < K; k0 += 8) {
        float4 av = *(const float4*)Aptr;  Aptr += 8;
        float4 bv = *(const float4*)Bptr;  Bptr += (size_t)8 * N;

        __syncthreads();   // previous tile fully consumed
        As[aCol + 0][aRow] = av.x;
        As[aCol + 1][aRow] = av.y;
        As[aCol + 2][aRow] = av.z;
        As[aCol + 3][aRow] = av.w;
        *(float4*)&Bs[bRow][bCol] = bv;
        __syncthreads();

        #pragma unroll
        for (int kk = 0; kk < 8; kk++) {
            float a[8], b[8];
            *(float4*)&a[0] = *(const float4*)&As[kk][mro];
            *(float4*)&a[4] = *(const float4*)&As[kk][mro + 4];
            *(float4*)&b[0] = *(const float4*)&Bs[kk][nco];
            *(float4*)&b[4] = *(const float4*)&Bs[kk][nco + 4];
            #pragma unroll
            for (int i = 0; i < 8; i++)
                #pragma unroll
                for (int j = 0; j < 8; j++)
                    acc[i][j] = fmaf(a[i], b[j], acc[i][j]);
        }
    }

    // Epilogue: bias (+ReLU) (+mask-prev zeroing)
    const int row0 = bm + mro;
    const int col0 = bn + nco;
    float bv[8];
    #pragma unroll
    for (int j = 0; j < 8; j++) bv[j] = bias[col0 + j];

    #pragma unroll
    for (int i = 0; i < 8; i++) {
        size_t base = (size_t)(row0 + i) * N + col0;
        #pragma unroll
        for (int j = 0; j < 8; j++) {
            float v = acc[i][j] + bv[j];
            if (do_relu) v = fmaxf(v, 0.0f);
            if (mask != nullptr && mask[base + j] > 0.0f) v = 0.0f;
            C[base + j] = v;
        }
    }
}

// ---------------------------------------------------------------------------
// Per-token exact top-256-of-1024 by energy = h*h, via 4-pass MSB radix
// select on the uint bit pattern (monotone for nonnegative floats).
// One block (256 threads) per token. Output: h where kept, else 0.
// Tie handling: entries strictly above threshold always kept; entries equal
// to threshold kept in index order up to the remaining budget (ties at a
// positive threshold are measure-zero; ties at zero have h == 0 anyway).
// ---------------------------------------------------------------------------
__global__ __launch_bounds__(256)
void topk_mask_kernel(const float* __restrict__ H, float* __restrict__ out)
{
    const int tid = threadIdx.x;
    const size_t row = (size_t)blockIdx.x * HDIM;

    __shared__ unsigned ebits[HDIM];
    __shared__ unsigned hist[256];
    __shared__ unsigned sc[256];
    __shared__ unsigned s_pref, s_r;

    float4 hv = ((const float4*)(H + row))[tid];   // elements 4*tid .. 4*tid+3
    float e0 = hv.x * hv.x, e1 = hv.y * hv.y, e2 = hv.z * hv.z, e3 = hv.w * hv.w;
    unsigned v0 = __float_as_uint(e0);
    unsigned v1 = __float_as_uint(e1);
    unsigned v2 = __float_as_uint(e2);
    unsigned v3 = __float_as_uint(e3);
    ebits[4 * tid + 0] = v0;
    ebits[4 * tid + 1] = v1;
    ebits[4 * tid + 2] = v2;
    ebits[4 * tid + 3] = v3;
    if (tid == 0) { s_pref = 0u; s_r = KSEL; }
    __syncthreads();

    #pragma unroll
    for (int pass = 0; pass < 4; pass++) {
        const int shift = 24 - 8 * pass;
        const unsigned pref = s_pref;
        const unsigned r    = s_r;
        hist[tid] = 0u;
        __syncthreads();

        #pragma unroll
        for (int j = 0; j < 4; j++) {
            unsigned v = ebits[4 * tid + j];
            bool cand = (pass == 0) || ((v >> (shift + 8)) == (pref >> (shift + 8)));
            if (cand) atomicAdd(&hist[(v >> shift) & 0xFFu], 1u);
        }
        __syncthreads();

        // suffix-inclusive scan: sc[b] = sum_{b' >= b} hist[b']
        sc[tid] = hist[tid];
        __syncthreads();
        for (int off = 1; off < 256; off <<= 1) {
            unsigned add = (tid + off < 256) ? sc[tid + off] : 0u;
            __syncthreads();
            sc[tid] += add;
            __syncthreads();
        }

        unsigned above = (tid == 255) ? 0u : sc[tid + 1];
        if (sc[tid] >= r && above < r) {       // unique bin (suffix monotone)
            s_pref = pref | ((unsigned)tid << shift);
            s_r    = r - above;
        }
        __syncthreads();
    }

    const unsigned thr  = s_pref;   // exact bit pattern of 256th-largest energy
    const unsigned need = s_r;      // how many entries EQUAL to thr to keep

    // index-ordered rank among equals: per-thread local count + block scan
    unsigned vv[4] = {v0, v1, v2, v3};
    unsigned pos[4];
    unsigned myc = 0;
    #pragma unroll
    for (int j = 0; j < 4; j++) {
        pos[j] = myc;
        myc += (vv[j] == thr) ? 1u : 0u;
    }
    sc[tid] = myc;
    __syncthreads();
    for (int off = 1; off < 256; off <<= 1) {
        unsigned add = (tid >= off) ? sc[tid - off] : 0u;
        __syncthreads();
        sc[tid] += add;
        __syncthreads();
    }
    const unsigned base = sc[tid] - myc;   // exclusive prefix of equals

    float h[4] = {hv.x, hv.y, hv.z, hv.w};
    float o[4];
    #pragma unroll
    for (int j = 0; j < 4; j++) {
        bool keep = (vv[j] > thr) || (vv[j] == thr && (base + pos[j]) < need);
        o[j] = keep ? h[j] : 0.0f;
    }
    ((float4*)(out + row))[tid] = make_float4(o[0], o[1], o[2], o[3]);
}

// ---------------------------------------------------------------------------
// kernel_launch
// ---------------------------------------------------------------------------
extern "C" void kernel_launch(void* const* d_in, const int* in_sizes, int n_in,
                              void* d_out, int out_size)
{
    const float* x         = (const float*)d_in[0];
    const float* mask_prev = (const float*)d_in[1];

    // Disambiguate input ordering at runtime:
    //  interleaved (setup_inputs dict order): x, mask, [e_w i, e_b i, d_w i, d_b i] x4
    //  sequential  (signature order):         x, mask, e_w0..e_b3, d_w0..d_b3
    // in_sizes[4]: interleaved -> d_w0 = 1024*512 = 524288; sequential -> e_w1 = 262144
    const bool inter = (in_sizes[4] == HDIM * 512);

    const float *ew[4], *eb[4], *dw[4], *db[4];
    for (int i = 0; i < 4; i++) {
        if (inter) {
            ew[i] = (const float*)d_in[2 + 4 * i];
            eb[i] = (const float*)d_in[3 + 4 * i];
            dw[i] = (const float*)d_in[4 + 4 * i];
            db[i] = (const float*)d_in[5 + 4 * i];
        } else {
            ew[i] = (const float*)d_in[2 + 2 * i];
            eb[i] = (const float*)d_in[3 + 2 * i];
            dw[i] = (const float*)d_in[10 + 2 * i];
            db[i] = (const float*)d_in[11 + 2 * i];
        }
    }

    float *bufA = nullptr, *bufB = nullptr;
    cudaGetSymbolAddress((void**)&bufA, g_bufA);
    cudaGetSymbolAddress((void**)&bufB, g_bufB);

    const int M = MTOK;
    dim3 blk(256);

    // Encoder
    {
        dim3 g(512 / 128, M / 128);
        sgemm_kernel<<<g, blk>>>(x,    ew[0], eb[0], nullptr, bufA, M, 512, 512, 1);
        sgemm_kernel<<<g, blk>>>(bufA, ew[1], eb[1], nullptr, bufB, M, 512, 512, 1);
        sgemm_kernel<<<g, blk>>>(bufB, ew[2], eb[2], nullptr, bufA, M, 512, 512, 1);
    }
    {
        dim3 g(HDIM / 128, M / 128);
        // last encoder layer: no relu, fuse mask_prev exclusion
        sgemm_kernel<<<g, blk>>>(bufA, ew[3], eb[3], mask_prev, bufB, M, HDIM, 512, 0);
    }

    // Top-k (256 of 1024) sparsification: bufB (h) -> bufA (masked h)
    topk_mask_kernel<<<MTOK, 256>>>(bufB, bufA);

    // Decoder
    {
        dim3 g(512 / 128, M / 128);
        sgemm_kernel<<<g, blk>>>(bufA, dw[0], db[0], nullptr, bufB, M, 512, HDIM, 1);
        sgemm_kernel<<<g, blk>>>(bufB, dw[1], db[1], nullptr, bufA, M, 512, 512, 1);
        sgemm_kernel<<<g, blk>>>(bufA, dw[2], db[2], nullptr, bufB, M, 512, 512, 1);
        sgemm_kernel<<<g, blk>>>(bufB, dw[3], db[3], nullptr, (float*)d_out, M, 512, 512, 0);
    }
}

// round 2
// speedup vs baseline: 1.0010x; 1.0010x over previous
#include <cuda_runtime.h>
#include <cuda_bf16.h>
#include <cstdint>

// Problem constants
#define MTOK   65536      // B*T = 16*4096
#define IDIM   512
#define HDIM   1024
#define KSEL   256        // 2*CDIM

// ---------------------------------------------------------------------------
// Scratch: two ping-pong activation buffers, each [65536, 1024] fp32 (256 MB).
// __device__ globals (no runtime allocation — allocation guards are enforced).
// ---------------------------------------------------------------------------
__device__ float g_bufA[(size_t)MTOK * HDIM];
__device__ float g_bufB[(size_t)MTOK * HDIM];

// ---------------------------------------------------------------------------
// SGEMM: C[M,N] = act( A[M,K] @ W[K,N] + bias[N] ), optional mask-zeroing.
// BM=BN=128, BK=8, 256 threads, 8x8 per-thread microtile.
// All dims are multiples of the tile sizes (M=65536, N in {512,1024},
// K in {512,1024}) -> no bounds checks.
// ---------------------------------------------------------------------------
__global__ __launch_bounds__(256)
void sgemm_kernel(const float* __restrict__ A, const float* __restrict__ W,
                  const float* __restrict__ bias, const float* __restrict__ mask,
                  float* __restrict__ C, int M, int N, int K, int do_relu)
{
    __shared__ __align__(16) float As[8][132];   // transposed A tile, padded
    __shared__ __align__(16) float Bs[8][132];   // B tile, padded

    const int tid = threadIdx.x;
    const int bm = blockIdx.y * 128;
    const int bn = blockIdx.x * 128;

    // A-tile load mapping: 128 rows x 8 cols = 256 float4 (one per thread)
    const int aRow = tid >> 1;            // 0..127
    const int aCol = (tid & 1) << 2;      // 0 or 4
    // B-tile load mapping: 8 rows x 128 cols = 256 float4
    const int bRow = tid >> 5;            // 0..7
    const int bCol = (tid & 31) << 2;     // 0..124

    const float* Aptr = A + (size_t)(bm + aRow) * K + aCol;
    const float* Bptr = W + (size_t)bRow * N + bn + bCol;

    const int tx = tid & 15;              // 0..15  -> col group
    const int ty = tid >> 4;              // 0..15  -> row group
    const int mro = ty * 8;
    const int nco = tx * 8;

    float acc[8][8];
    #pragma unroll
    for (int i = 0; i < 8; i++)
        #pragma unroll
        for (int j = 0; j < 8; j++) acc[i][j] = 0.0f;

    for (int k0 = 0; k0 < K; k0 += 8) {
        float4 av = *(const float4*)Aptr;  Aptr += 8;
        float4 bv = *(const float4*)Bptr;  Bptr += (size_t)8 * N;

        __syncthreads();   // previous tile fully consumed
        As[aCol + 0][aRow] = av.x;
        As[aCol + 1][aRow] = av.y;
        As[aCol + 2][aRow] = av.z;
        As[aCol + 3][aRow] = av.w;
        *(float4*)&Bs[bRow][bCol] = bv;
        __syncthreads();

        #pragma unroll
        for (int kk = 0; kk < 8; kk++) {
            float a[8], b[8];
            *(float4*)&a[0] = *(const float4*)&As[kk][mro];
            *(float4*)&a[4] = *(const float4*)&As[kk][mro + 4];
            *(float4*)&b[0] = *(const float4*)&Bs[kk][nco];
            *(float4*)&b[4] = *(const float4*)&Bs[kk][nco + 4];
            #pragma unroll
            for (int i = 0; i < 8; i++)
                #pragma unroll
                for (int j = 0; j < 8; j++)
                    acc[i][j] = fmaf(a[i], b[j], acc[i][j]);
        }
    }

    // Epilogue: bias (+ReLU) (+mask-prev zeroing)
    const int row0 = bm + mro;
    const int col0 = bn + nco;
    float bv[8];
    #pragma unroll
    for (int j = 0; j < 8; j++) bv[j] = bias[col0 + j];

    #pragma unroll
    for (int i = 0; i < 8; i++) {
        size_t base = (size_t)(row0 + i) * N + col0;
        #pragma unroll
        for (int j = 0; j < 8; j++) {
            float v = acc[i][j] + bv[j];
            if (do_relu) v = fmaxf(v, 0.0f);
            if (mask != nullptr && mask[base + j] > 0.0f) v = 0.0f;
            C[base + j] = v;
        }
    }
}

// ---------------------------------------------------------------------------
// Per-token exact top-256-of-1024 by energy = h*h, via 4-pass MSB radix
// select on the uint bit pattern (monotone for nonnegative floats).
// One block (256 threads) per token. Output: h where kept, else 0.
// Tie handling: entries strictly above threshold always kept; entries equal
// to threshold kept in index order up to the remaining budget (ties at a
// positive threshold are measure-zero; ties at zero have h == 0 anyway).
// ---------------------------------------------------------------------------
__global__ __launch_bounds__(256)
void topk_mask_kernel(const float* __restrict__ H, float* __restrict__ out)
{
    const int tid = threadIdx.x;
    const size_t row = (size_t)blockIdx.x * HDIM;

    __shared__ unsigned ebits[HDIM];
    __shared__ unsigned hist[256];
    __shared__ unsigned sc[256];
    __shared__ unsigned s_pref, s_r;

    float4 hv = ((const float4*)(H + row))[tid];   // elements 4*tid .. 4*tid+3
    float e0 = hv.x * hv.x, e1 = hv.y * hv.y, e2 = hv.z * hv.z, e3 = hv.w * hv.w;
    unsigned v0 = __float_as_uint(e0);
    unsigned v1 = __float_as_uint(e1);
    unsigned v2 = __float_as_uint(e2);
    unsigned v3 = __float_as_uint(e3);
    ebits[4 * tid + 0] = v0;
    ebits[4 * tid + 1] = v1;
    ebits[4 * tid + 2] = v2;
    ebits[4 * tid + 3] = v3;
    if (tid == 0) { s_pref = 0u; s_r = KSEL; }
    __syncthreads();

    #pragma unroll
    for (int pass = 0; pass < 4; pass++) {
        const int shift = 24 - 8 * pass;
        const unsigned pref = s_pref;
        const unsigned r    = s_r;
        hist[tid] = 0u;
        __syncthreads();

        #pragma unroll
        for (int j = 0; j < 4; j++) {
            unsigned v = ebits[4 * tid + j];
            bool cand = (pass == 0) || ((v >> (shift + 8)) == (pref >> (shift + 8)));
            if (cand) atomicAdd(&hist[(v >> shift) & 0xFFu], 1u);
        }
        __syncthreads();

        // suffix-inclusive scan: sc[b] = sum_{b' >= b} hist[b']
        sc[tid] = hist[tid];
        __syncthreads();
        for (int off = 1; off < 256; off <<= 1) {
            unsigned add = (tid + off < 256) ? sc[tid + off] : 0u;
            __syncthreads();
            sc[tid] += add;
            __syncthreads();
        }

        unsigned above = (tid == 255) ? 0u : sc[tid + 1];
        if (sc[tid] >= r && above < r) {       // unique bin (suffix monotone)
            s_pref = pref | ((unsigned)tid << shift);
            s_r    = r - above;
        }
        __syncthreads();
    }

    const unsigned thr  = s_pref;   // exact bit pattern of 256th-largest energy
    const unsigned need = s_r;      // how many entries EQUAL to thr to keep

    // index-ordered rank among equals: per-thread local count + block scan
    unsigned vv[4] = {v0, v1, v2, v3};
    unsigned pos[4];
    unsigned myc = 0;
    #pragma unroll
    for (int j = 0; j < 4; j++) {
        pos[j] = myc;
        myc += (vv[j] == thr) ? 1u : 0u;
    }
    sc[tid] = myc;
    __syncthreads();
    for (int off = 1; off < 256; off <<= 1) {
        unsigned add = (tid >= off) ? sc[tid - off] : 0u;
        __syncthreads();
        sc[tid] += add;
        __syncthreads();
    }
    const unsigned base = sc[tid] - myc;   // exclusive prefix of equals

    float h[4] = {hv.x, hv.y, hv.z, hv.w};
    float o[4];
    #pragma unroll
    for (int j = 0; j < 4; j++) {
        bool keep = (vv[j] > thr) || (vv[j] == thr && (base + pos[j]) < need);
        o[j] = keep ? h[j] : 0.0f;
    }
    ((float4*)(out + row))[tid] = make_float4(o[0], o[1], o[2], o[3]);
}

// ---------------------------------------------------------------------------
// kernel_launch
// ---------------------------------------------------------------------------
extern "C" void kernel_launch(void* const* d_in, const int* in_sizes, int n_in,
                              void* d_out, int out_size)
{
    const float* x         = (const float*)d_in[0];
    const float* mask_prev = (const float*)d_in[1];

    // Disambiguate input ordering at runtime:
    //  interleaved (setup_inputs dict order): x, mask, [e_w i, e_b i, d_w i, d_b i] x4
    //  sequential  (signature order):         x, mask, e_w0..e_b3, d_w0..d_b3
    // in_sizes[4]: interleaved -> d_w0 = 1024*512 = 524288; sequential -> e_w1 = 262144
    const bool inter = (in_sizes[4] == HDIM * 512);

    const float *ew[4], *eb[4], *dw[4], *db[4];
    for (int i = 0; i < 4; i++) {
        if (inter) {
            ew[i] = (const float*)d_in[2 + 4 * i];
            eb[i] = (const float*)d_in[3 + 4 * i];
            dw[i] = (const float*)d_in[4 + 4 * i];
            db[i] = (const float*)d_in[5 + 4 * i];
        } else {
            ew[i] = (const float*)d_in[2 + 2 * i];
            eb[i] = (const float*)d_in[3 + 2 * i];
            dw[i] = (const float*)d_in[10 + 2 * i];
            db[i] = (const float*)d_in[11 + 2 * i];
        }
    }

    float *bufA = nullptr, *bufB = nullptr;
    cudaGetSymbolAddress((void**)&bufA, g_bufA);
    cudaGetSymbolAddress((void**)&bufB, g_bufB);

    const int M = MTOK;
    dim3 blk(256);

    // Encoder
    {
        dim3 g(512 / 128, M / 128);
        sgemm_kernel<<<g, blk>>>(x,    ew[0], eb[0], nullptr, bufA, M, 512, 512, 1);
        sgemm_kernel<<<g, blk>>>(bufA, ew[1], eb[1], nullptr, bufB, M, 512, 512, 1);
        sgemm_kernel<<<g, blk>>>(bufB, ew[2], eb[2], nullptr, bufA, M, 512, 512, 1);
    }
    {
        dim3 g(HDIM / 128, M / 128);
        // last encoder layer: no relu, fuse mask_prev exclusion
        sgemm_kernel<<<g, blk>>>(bufA, ew[3], eb[3], mask_prev, bufB, M, HDIM, 512, 0);
    }

    // Top-k (256 of 1024) sparsification: bufB (h) -> bufA (masked h)
    topk_mask_kernel<<<MTOK, 256>>>(bufB, bufA);

    // Decoder
    {
        dim3 g(512 / 128, M / 128);
        sgemm_kernel<<<g, blk>>>(bufA, dw[0], db[0], nullptr, bufB, M, 512, HDIM, 1);
        sgemm_kernel<<<g, blk>>>(bufB, dw[1], db[1], nullptr, bufA, M, 512, 512, 1);
        sgemm_kernel<<<g, blk>>>(bufA, dw[2], db[2], nullptr, bufB, M, 512, 512, 1);
        sgemm_kernel<<<g, blk>>>(bufB, dw[3], db[3], nullptr, (float*)d_out, M, 512, 512, 0);
    }
}